// round 16
// baseline (speedup 1.0000x reference)
#include <cuda_runtime.h>
#include <cuda_fp16.h>
#include <math.h>
#include <stdint.h>

// FourierAttention R16: scores split into 256-thread jh-CTAs (re/im) so 2 CTAs
// co-reside per SM (latency hiding like v_gemm). Q/K converted to fp16 at LDG
// time to keep held registers low. jh pairs share L2 footprint.
// B=4, L=8192, H=16, D=64, Ls=64, M=128.

#define BDIM 4
#define LDIM 8192
#define HDIM 16
#define DDIM 64
#define LSEG 64
#define MSEG 128
#define BH   64
#define KDIM 4096
#define KCH  2
#define LPB  16
#define ROWSTRIDE 1024
#define SEGSTRIDE 65536
#define BSTRIDE (LDIM*ROWSTRIDE)

// Scratch (device globals: allocation-free, graph-capture safe)
__device__ float g_Cpart[(size_t)KCH * BH * MSEG * 256]; // score partials
__device__ __half g_Ah[(size_t)BH * MSEG * MSEG];        // softmax result (fp16)

__device__ __forceinline__ void mma_f16(float* d, const unsigned* a,
                                        unsigned b0, unsigned b1) {
    asm volatile(
        "mma.sync.aligned.m16n8k16.row.col.f32.f16.f16.f32 "
        "{%0,%1,%2,%3},{%4,%5,%6,%7},{%8,%9},{%0,%1,%2,%3};"
        : "+f"(d[0]), "+f"(d[1]), "+f"(d[2]), "+f"(d[3])
        : "r"(a[0]), "r"(a[1]), "r"(a[2]), "r"(a[3]), "r"(b0), "r"(b1));
}

__device__ __forceinline__ unsigned h2u(float a, float b) {
    __half2 h = __floats2half2_rn(a, b);
    return *(unsigned*)&h;
}

__device__ __forceinline__ uint32_t smem_u32(const void* p) {
    uint32_t a;
    asm("{ .reg .u64 t; cvta.to.shared.u64 t, %1; cvt.u32.u64 %0, t; }" : "=r"(a) : "l"(p));
    return a;
}

__device__ __forceinline__ void ldsm_x4(unsigned* r, uint32_t addr) {
    asm volatile("ldmatrix.sync.aligned.m8n8.x4.shared.b16 {%0,%1,%2,%3}, [%4];"
        : "=r"(r[0]), "=r"(r[1]), "=r"(r[2]), "=r"(r[3]) : "r"(addr));
}

// smem layout (halves): 2 buffers of [As 128x72 | Bs 128x72], Apar, taps
#define AS_L 0
#define BS_L (128 * 72)                 // 9216, buffer-local
#define BUFH (2 * 128 * 72)             // 18432 halves per buffer
#define AP_H (2 * BUFH)                 // 36864: Apar[2][128][40] (jh=1 only)
#define TP_H (AP_H + 2 * 128 * 40)      // 47104: taps[2][32][40]
#define TOT_H (TP_H + 2 * 32 * 40)      // 49664 halves
#define SS_SMEM (TOT_H * 2)             // 99328 bytes

__global__ __launch_bounds__(256, 2) void scores_split(const float* __restrict__ q,
                                                       const float* __restrict__ kin) {
    extern __shared__ __half sh[];

    int kc = blockIdx.x >> 1;
    int jh = blockIdx.x & 1;
    int bh = blockIdx.y;
    int b  = bh >> 4, h = bh & 15;
    int tid  = threadIdx.x;
    int lane = tid & 31;
    int w    = tid >> 5;
    int g = lane >> 2, t4 = lane & 3;
    int m0 = (w >> 1) * 32;
    int j0 = (w & 1) * 64;

    // taps (jh=1 only)
    if (jh == 1) {
        for (int i = tid; i < 2048; i += 256) {
            int which = i >> 10, dd = (i >> 5) & 31, tt = i & 31;
            int delta = which ? (2 * dd + 1 - 2 * tt) : (2 * dd - 2 * tt - 1);
            float x = (float)delta * (1.0f / 64.0f);
            sh[TP_H + which * 1280 + dd * 40 + tt] =
                __float2half(-(cospif(x) / sinpif(x)) * (1.0f / 64.0f));
        }
    }

    float dacc[2][8][4];
#pragma unroll
    for (int mi = 0; mi < 2; mi++)
#pragma unroll
        for (int nj = 0; nj < 8; nj++)
#pragma unroll
            for (int r = 0; r < 4; r++) dacc[mi][nj][r] = 0.0f;

    const float* qb = q   + (size_t)b * BSTRIDE + h * DDIM;
    const float* kb = kin + (size_t)b * BSTRIDE + h * DDIM;

    // staging: 2 threads per row
    int n    = tid >> 1;
    int q32f = (tid & 1) * 32;

    uint32_t sb = smem_u32(sh);
    // main-MMA ldsm byte offsets (buffer-local)
    uint32_t offA[2], offB[4];
#pragma unroll
    for (int mi = 0; mi < 2; mi++) {
        int row = m0 + mi * 16 + (lane & 7) + ((lane >> 3) & 1) * 8;
        int col = ((lane >> 4) & 1) * 8;
        offA[mi] = (uint32_t)(AS_L + row * 72 + col) * 2;
    }
#pragma unroll
    for (int njp = 0; njp < 4; njp++) {
        int row = j0 + njp * 16 + (lane & 7) + ((lane >> 4) & 1) * 8;
        int col = ((lane >> 3) & 1) * 8;
        offB[njp] = (uint32_t)(BS_L + row * 72 + col) * 2;
    }
    // transform offsets (jh=1): warp w covers 16 n-rows, both parities
    int nblk  = w * 16;
    int arow_ = nblk + (lane & 7) + ((lane >> 3) & 1) * 8;
    int acol_ = ((lane >> 4) & 1) * 8;
    int brow_ = (lane & 7) + ((lane >> 4) & 1) * 8;
    int bcol_ = ((lane >> 3) & 1) * 8;

    int l0 = kc * 32;
    unsigned qh[16], rh[16];

#define LDG_IT(LIDX)                                                           \
    {                                                                          \
        const float* sq_ = qb + (size_t)(n * LSEG + (LIDX)) * ROWSTRIDE + q32f;\
        const float* sk_ = kb + (size_t)(n * LSEG + (LIDX)) * ROWSTRIDE + q32f;\
        float4 kvv[8];                                                         \
        _Pragma("unroll")                                                      \
        for (int i_ = 0; i_ < 8; i_++) {                                       \
            float4 v_ = *(const float4*)(sq_ + 4 * i_);                        \
            qh[2 * i_]     = h2u(v_.x, v_.y);                                  \
            qh[2 * i_ + 1] = h2u(v_.z, v_.w);                                  \
            kvv[i_] = *(const float4*)(sk_ + 4 * i_);                          \
        }                                                                      \
        if (jh == 0) {                                                         \
            float se_ = 0.0f, so_ = 0.0f;                                      \
            _Pragma("unroll")                                                  \
            for (int i_ = 0; i_ < 8; i_++) {                                   \
                se_ += kvv[i_].x + kvv[i_].z;                                  \
                so_ += kvv[i_].y + kvv[i_].w;                                  \
            }                                                                  \
            se_ += __shfl_xor_sync(0xffffffffu, se_, 1);                       \
            so_ += __shfl_xor_sync(0xffffffffu, so_, 1);                       \
            se_ *= (1.0f / 64.0f);                                             \
            so_ *= (1.0f / 64.0f);                                             \
            _Pragma("unroll")                                                  \
            for (int i_ = 0; i_ < 8; i_++) {                                   \
                rh[2 * i_]     = h2u(0.5f * kvv[i_].x + se_, 0.5f * kvv[i_].y + so_); \
                rh[2 * i_ + 1] = h2u(0.5f * kvv[i_].z + se_, 0.5f * kvv[i_].w + so_); \
            }                                                                  \
        } else {                                                               \
            _Pragma("unroll")                                                  \
            for (int i_ = 0; i_ < 8; i_++) {                                   \
                rh[i_]     = h2u(kvv[i_].x, kvv[i_].z);                        \
                rh[8 + i_] = h2u(kvv[i_].y, kvv[i_].w);                        \
            }                                                                  \
        }                                                                      \
    }

#define STAGE(BUF)                                                             \
    {                                                                          \
        __half* bufp = sh + (BUF) * BUFH;                                      \
        _Pragma("unroll")                                                      \
        for (int u_ = 0; u_ < 4; u_++)                                         \
            *(uint4*)&bufp[AS_L + n * 72 + q32f + 8 * u_] = *(uint4*)&qh[4 * u_]; \
        if (jh == 0) {                                                         \
            _Pragma("unroll")                                                  \
            for (int u_ = 0; u_ < 4; u_++)                                     \
                *(uint4*)&bufp[BS_L + n * 72 + q32f + 8 * u_] = *(uint4*)&rh[4 * u_]; \
        } else {                                                               \
            __half* app = sh + AP_H;                                           \
            int po_ = (tid & 1) * 16;                                          \
            *(uint4*)&app[n * 40 + po_]            = *(uint4*)&rh[0];          \
            *(uint4*)&app[n * 40 + po_ + 8]        = *(uint4*)&rh[4];          \
            *(uint4*)&app[5120 + n * 40 + po_]     = *(uint4*)&rh[8];          \
            *(uint4*)&app[5120 + n * 40 + po_ + 8] = *(uint4*)&rh[12];         \
        }                                                                      \
    }

#define TRANSFORM(BUF)                                                         \
    {                                                                          \
        __half* bsim = sh + (BUF) * BUFH + BS_L;                               \
        _Pragma("unroll")                                                      \
        for (int P_ = 0; P_ < 2; P_++) {                                       \
            float cacc[4][4];                                                  \
            _Pragma("unroll")                                                  \
            for (int j8_ = 0; j8_ < 4; j8_++)                                  \
                _Pragma("unroll")                                              \
                for (int r_ = 0; r_ < 4; r_++) cacc[j8_][r_] = 0.0f;           \
            uint32_t offTA = sb + (uint32_t)(AP_H + (1 - P_) * 5120 +          \
                                             arow_ * 40 + acol_) * 2;          \
            uint32_t offTB = sb + (uint32_t)(TP_H + P_ * 1280 +                \
                                             brow_ * 40 + bcol_) * 2;          \
            _Pragma("unroll")                                                  \
            for (int s_ = 0; s_ < 2; s_++) {                                   \
                unsigned a_[4];                                                \
                ldsm_x4(a_, offTA + s_ * 32);                                  \
                _Pragma("unroll")                                              \
                for (int dt_ = 0; dt_ < 2; dt_++) {                            \
                    unsigned bb_[4];                                           \
                    ldsm_x4(bb_, offTB + dt_ * 1280 + s_ * 32);                \
                    mma_f16(cacc[dt_ * 2 + 0], a_, bb_[0], bb_[1]);            \
                    mma_f16(cacc[dt_ * 2 + 1], a_, bb_[2], bb_[3]);            \
                }                                                              \
            }                                                                  \
            _Pragma("unroll")                                                  \
            for (int j8_ = 0; j8_ < 4; j8_++) {                                \
                int col0_ = P_ + 2 * (j8_ * 8 + 2 * t4);                       \
                int row_  = nblk + g;                                          \
                bsim[row_ * 72 + col0_]           = __float2half(cacc[j8_][0]); \
                bsim[row_ * 72 + col0_ + 2]       = __float2half(cacc[j8_][1]); \
                bsim[(row_ + 8) * 72 + col0_]     = __float2half(cacc[j8_][2]); \
                bsim[(row_ + 8) * 72 + col0_ + 2] = __float2half(cacc[j8_][3]); \
            }                                                                  \
        }                                                                      \
    }

#define MAIN_MMA(BUF)                                                          \
    {                                                                          \
        uint32_t bb0 = sb + (uint32_t)((BUF) * BUFH) * 2;                      \
        _Pragma("unroll")                                                      \
        for (int s_ = 0; s_ < 4; s_++) {                                       \
            uint32_t so_ = s_ * 32;                                            \
            unsigned a_[2][4];                                                 \
            _Pragma("unroll")                                                  \
            for (int mi_ = 0; mi_ < 2; mi_++) ldsm_x4(a_[mi_], bb0 + offA[mi_] + so_); \
            _Pragma("unroll")                                                  \
            for (int njp_ = 0; njp_ < 4; njp_++) {                             \
                unsigned bbv_[4];                                              \
                ldsm_x4(bbv_, bb0 + offB[njp_] + so_);                         \
                _Pragma("unroll")                                              \
                for (int mi_ = 0; mi_ < 2; mi_++) {                            \
                    mma_f16(dacc[mi_][2 * njp_],     a_[mi_], bbv_[0], bbv_[1]); \
                    mma_f16(dacc[mi_][2 * njp_ + 1], a_[mi_], bbv_[2], bbv_[3]); \
                }                                                              \
            }                                                                  \
        }                                                                      \
    }

    if (jh == 0) {
        // 1 barrier per iteration
        LDG_IT(l0);
        STAGE(0);
        LDG_IT(l0 + 1);
        __syncthreads();
        for (int il = 0; il < 32; il++) {
            int buf = il & 1;
            if (il + 1 < 32) {
                STAGE(buf ^ 1);
                if (il + 2 < 32) LDG_IT(l0 + il + 2);
            }
            MAIN_MMA(buf);
            __syncthreads();
        }
    } else {
        // 2 barriers per iteration (Apar discipline)
        LDG_IT(l0);
        STAGE(0);
        LDG_IT(l0 + 1);
        __syncthreads();          // As(0) + Apar(l0) + taps visible
        TRANSFORM(0);
        __syncthreads();          // Bs-im(0) visible
        for (int il = 0; il < 32; il++) {
            int buf = il & 1;
            if (il + 1 < 32) {
                STAGE(buf ^ 1);
                if (il + 2 < 32) LDG_IT(l0 + il + 2);
            }
            MAIN_MMA(buf);
            __syncthreads();       // Apar(l0+il+1) visible; buf^1 readers done
            if (il + 1 < 32) {
                TRANSFORM(buf ^ 1);
                __syncthreads();   // Bs-im(buf^1) visible
            }
        }
    }

    float* cp = g_Cpart + ((size_t)(kc * BH + bh) * MSEG) * 256 + (size_t)jh * 128;
#pragma unroll
    for (int mi = 0; mi < 2; mi++) {
#pragma unroll
        for (int nj = 0; nj < 8; nj++) {
            int r = m0 + mi * 16 + g;
            int c = j0 + nj * 8 + 2 * t4;
            *(float2*)(cp + (size_t)r * 256 + c)       = make_float2(dacc[mi][nj][0], dacc[mi][nj][1]);
            *(float2*)(cp + (size_t)(r + 8) * 256 + c) = make_float2(dacc[mi][nj][2], dacc[mi][nj][3]);
        }
    }
}

// ---------------------------------------------------------------------------
// Kernel 2: reduce partials, |S|/512, row softmax -> g_Ah (fp16)
// ---------------------------------------------------------------------------
__global__ __launch_bounds__(256) void softmax_k() {
    int bh   = blockIdx.x;
    int m    = blockIdx.y * 8 + (threadIdx.x >> 5);
    int lane = threadIdx.x & 31;

    float t[4];
#pragma unroll
    for (int u = 0; u < 4; u++) {
        int n = lane + u * 32;
        float sre = 0.0f, sim = 0.0f;
#pragma unroll
        for (int p = 0; p < KCH; p++) {
            const float* cp = g_Cpart + (((size_t)p * BH + bh) * MSEG + m) * 256;
            sre += cp[n];
            sim += cp[n + 128];
        }
        t[u] = sqrtf(sre * sre + sim * sim) * (1.0f / 512.0f);
    }
    float mx = fmaxf(fmaxf(t[0], t[1]), fmaxf(t[2], t[3]));
#pragma unroll
    for (int o = 16; o; o >>= 1) mx = fmaxf(mx, __shfl_xor_sync(0xffffffffu, mx, o));
    float e[4], s = 0.0f;
#pragma unroll
    for (int u = 0; u < 4; u++) { e[u] = expf(t[u] - mx); s += e[u]; }
#pragma unroll
    for (int o = 16; o; o >>= 1) s += __shfl_xor_sync(0xffffffffu, s, o);
    float inv = 1.0f / s;
    __half* arow = g_Ah + ((size_t)bh * MSEG + m) * MSEG;
#pragma unroll
    for (int u = 0; u < 4; u++) arow[lane + u * 32] = __float2half(e[u] * inv);
}

// ---------------------------------------------------------------------------
// Kernel 3: out = A @ v, FP16 mma. A resident, LPB=16, single sync per l.
// grid 256 = one resident wave at 2 CTA/SM.  (unchanged from R15)
// ---------------------------------------------------------------------------
__global__ __launch_bounds__(256, 2) void v_gemm_h3(const float* __restrict__ v,
                                                    float* __restrict__ out) {
    extern __shared__ char dynsm[];
    __half (*As)[136]  = (__half(*)[136])dynsm;
    __half2 (*vsp)[72] = (__half2(*)[72])(dynsm + 128 * 136 * 2);

    int bx = blockIdx.x;
    int lg = bx & 3;
    int bh = bx >> 2;
    int b  = bh >> 4, h = bh & 15;
    int tid  = threadIdx.x;
    int lane = tid & 31;
    int w    = tid >> 5;
    int g = lane >> 2, t = lane & 3;
    int m0 = (w >> 1) * 32;
    int d0 = (w & 1) * 32;

    const __half* Abase = g_Ah + (size_t)bh * MSEG * MSEG;
    const float* vbh    = v + (size_t)b * BSTRIDE + h * DDIM;
    float* obh          = out + (size_t)b * BSTRIDE + h * DDIM;

    int kpV = tid >> 4;
    int d4V = tid & 15;

    float4 pv[8];
    {
        const float* vb = vbh + (size_t)(lg * LPB) * ROWSTRIDE;
#pragma unroll
        for (int i = 0; i < 4; i++) {
            int kp = kpV + 16 * i;
            pv[2 * i]     = *(const float4*)(vb + (size_t)(2 * kp) * SEGSTRIDE + d4V * 4);
            pv[2 * i + 1] = *(const float4*)(vb + (size_t)(2 * kp + 1) * SEGSTRIDE + d4V * 4);
        }
    }

#pragma unroll
    for (int i = 0; i < 8; i++) {
        int idx = tid + i * 256;
        int m = idx >> 4, c = idx & 15;
        uint4 u = *(const uint4*)(Abase + (size_t)m * MSEG + c * 8);
        *(uint4*)&As[m][c * 8] = u;
    }

    for (int il = 0; il < LPB; il++) {
        int l   = lg * LPB + il;
        int buf = (il & 1) * 64;
#pragma unroll
        for (int i = 0; i < 4; i++) {
            int kp = kpV + 16 * i;
            uint4 u;
            u.x = h2u(pv[2 * i].x, pv[2 * i + 1].x);
            u.y = h2u(pv[2 * i].y, pv[2 * i + 1].y);
            u.z = h2u(pv[2 * i].z, pv[2 * i + 1].z);
            u.w = h2u(pv[2 * i].w, pv[2 * i + 1].w);
            *(uint4*)&vsp[buf + kp][d4V * 4] = u;
        }
        if (il + 1 < LPB) {
            const float* vb = vbh + (size_t)(l + 1) * ROWSTRIDE;
#pragma unroll
            for (int i = 0; i < 4; i++) {
                int kp = kpV + 16 * i;
                pv[2 * i]     = *(const float4*)(vb + (size_t)(2 * kp) * SEGSTRIDE + d4V * 4);
                pv[2 * i + 1] = *(const float4*)(vb + (size_t)(2 * kp + 1) * SEGSTRIDE + d4V * 4);
            }
        }
        __syncthreads();

        float dacc[2][4][4];
#pragma unroll
        for (int mi = 0; mi < 2; mi++)
#pragma unroll
            for (int dj = 0; dj < 4; dj++)
#pragma unroll
                for (int r = 0; r < 4; r++) dacc[mi][dj][r] = 0.0f;

#pragma unroll
        for (int s = 0; s < 8; s++) {
            int kb16 = s * 16;
            unsigned bb[4][2];
#pragma unroll
            for (int dj = 0; dj < 4; dj++) {
                int c = d0 + dj * 8 + g;
                bb[dj][0] = *(const unsigned*)&vsp[buf + s * 8 + t][c];
                bb[dj][1] = *(const unsigned*)&vsp[buf + s * 8 + t + 4][c];
            }
#pragma unroll
            for (int mi = 0; mi < 2; mi++) {
                int r = m0 + mi * 16 + g;
                unsigned a[4];
                a[0] = *(const unsigned*)&As[r][kb16 + 2 * t];
                a[1] = *(const unsigned*)&As[r + 8][kb16 + 2 * t];
                a[2] = *(const unsigned*)&As[r][kb16 + 2 * t + 8];
                a[3] = *(const unsigned*)&As[r + 8][kb16 + 2 * t + 8];
#pragma unroll
                for (int dj = 0; dj < 4; dj++) mma_f16(dacc[mi][dj], a, bb[dj][0], bb[dj][1]);
            }
        }

        float* obase = obh + (size_t)l * ROWSTRIDE;
#pragma unroll
        for (int mi = 0; mi < 2; mi++) {
#pragma unroll
            for (int dj = 0; dj < 4; dj++) {
                int r = m0 + mi * 16 + g;
                int c = d0 + dj * 8 + 2 * t;
                *(float2*)(obase + (size_t)r * SEGSTRIDE + c)       = make_float2(dacc[mi][dj][0], dacc[mi][dj][1]);
                *(float2*)(obase + (size_t)(r + 8) * SEGSTRIDE + c) = make_float2(dacc[mi][dj][2], dacc[mi][dj][3]);
            }
        }
    }
}

#define VG_SMEM (128 * 136 * 2 + 2 * 64 * 72 * 4)

// ---------------------------------------------------------------------------
extern "C" void kernel_launch(void* const* d_in, const int* in_sizes, int n_in,
                              void* d_out, int out_size) {
    const float* q = (const float*)d_in[0];
    const float* k = (const float*)d_in[1];
    const float* v = (const float*)d_in[2];
    float* out = (float*)d_out;

    cudaFuncSetAttribute(scores_split, cudaFuncAttributeMaxDynamicSharedMemorySize, SS_SMEM);
    cudaFuncSetAttribute(v_gemm_h3, cudaFuncAttributeMaxDynamicSharedMemorySize, VG_SMEM);

    scores_split<<<dim3(2 * KCH, BH), 256, SS_SMEM>>>(q, k);
    softmax_k<<<dim3(BH, 16), 256>>>();
    v_gemm_h3<<<BH * (LSEG / LPB), 256, VG_SMEM>>>(v, out);
}

// round 17
// speedup vs baseline: 1.7598x; 1.7598x over previous
#include <cuda_runtime.h>
#include <cuda_fp16.h>
#include <math.h>
#include <stdint.h>

// FourierAttention R17: R15 structure (proven best) + fp16 score partials
// (halves Cpart round-trip traffic). B=4, L=8192, H=16, D=64, Ls=64, M=128.

#define BDIM 4
#define LDIM 8192
#define HDIM 16
#define DDIM 64
#define LSEG 64
#define MSEG 128
#define BH   64
#define KDIM 4096
#define KCH  2
#define LPB  16
#define ROWSTRIDE 1024
#define SEGSTRIDE 65536
#define BSTRIDE (LDIM*ROWSTRIDE)

// Scratch (device globals: allocation-free, graph-capture safe)
__device__ __half g_CpartH[(size_t)KCH * BH * MSEG * 256]; // fp16 score partials
__device__ __half g_Ah[(size_t)BH * MSEG * MSEG];          // softmax result (fp16)

__device__ __forceinline__ void mma_f16(float* d, const unsigned* a,
                                        unsigned b0, unsigned b1) {
    asm volatile(
        "mma.sync.aligned.m16n8k16.row.col.f32.f16.f16.f32 "
        "{%0,%1,%2,%3},{%4,%5,%6,%7},{%8,%9},{%0,%1,%2,%3};"
        : "+f"(d[0]), "+f"(d[1]), "+f"(d[2]), "+f"(d[3])
        : "r"(a[0]), "r"(a[1]), "r"(a[2]), "r"(a[3]), "r"(b0), "r"(b1));
}

__device__ __forceinline__ unsigned h2u(float a, float b) {
    __half2 h = __floats2half2_rn(a, b);
    return *(unsigned*)&h;
}

__device__ __forceinline__ uint32_t smem_u32(const void* p) {
    uint32_t a;
    asm("{ .reg .u64 t; cvta.to.shared.u64 t, %1; cvt.u32.u64 %0, t; }" : "=r"(a) : "l"(p));
    return a;
}

__device__ __forceinline__ void ldsm_x4(unsigned* r, uint32_t addr) {
    asm volatile("ldmatrix.sync.aligned.m8n8.x4.shared.b16 {%0,%1,%2,%3}, [%4];"
        : "=r"(r[0]), "=r"(r[1]), "=r"(r[2]), "=r"(r[3]) : "r"(addr));
}

// smem layout (halves): 2 buffers of [As 128x72 | Bs 256x72], Apar, taps
#define AS_L 0
#define BS_L (128 * 72)
#define BUFH ((128 + 256) * 72)
#define AP_H (2 * BUFH)
#define TP_H (AP_H + 2 * 128 * 40)
#define TOT_H (TP_H + 2 * 32 * 40)
#define FS_SMEM (TOT_H * 2)             // 136192 bytes

__global__ __launch_bounds__(512, 1) void scores_fused3(const float* __restrict__ q,
                                                        const float* __restrict__ kin) {
    extern __shared__ __half sh[];

    int kc = blockIdx.x;
    int bh = blockIdx.y;
    int b  = bh >> 4, h = bh & 15;
    int tid  = threadIdx.x;
    int lane = tid & 31;
    int w    = tid >> 5;
    int g = lane >> 2, t4 = lane & 3;
    int m0 = (w >> 2) * 32;
    int j0 = (w & 3) * 64;

#pragma unroll
    for (int i = tid; i < 2048; i += 512) {
        int which = i >> 10, dd = (i >> 5) & 31, tt = i & 31;
        int delta = which ? (2 * dd + 1 - 2 * tt) : (2 * dd - 2 * tt - 1);
        float x = (float)delta * (1.0f / 64.0f);
        sh[TP_H + which * 1280 + dd * 40 + tt] =
            __float2half(-(cospif(x) / sinpif(x)) * (1.0f / 64.0f));
    }

    float dacc[2][8][4];
#pragma unroll
    for (int mi = 0; mi < 2; mi++)
#pragma unroll
        for (int nj = 0; nj < 8; nj++)
#pragma unroll
            for (int r = 0; r < 4; r++) dacc[mi][nj][r] = 0.0f;

    const float* qb = q   + (size_t)b * BSTRIDE + h * DDIM;
    const float* kb = kin + (size_t)b * BSTRIDE + h * DDIM;

    int n   = tid >> 2;
    int q16 = (tid & 3) * 16;
    int q8  = (tid & 3) * 8;

    uint32_t sb = smem_u32(sh);
    uint32_t offA[2], offB[4];
#pragma unroll
    for (int mi = 0; mi < 2; mi++) {
        int row = m0 + mi * 16 + (lane & 7) + ((lane >> 3) & 1) * 8;
        int col = ((lane >> 4) & 1) * 8;
        offA[mi] = (uint32_t)(AS_L + row * 72 + col) * 2;
    }
#pragma unroll
    for (int njp = 0; njp < 4; njp++) {
        int row = j0 + njp * 16 + (lane & 7) + ((lane >> 4) & 1) * 8;
        int col = ((lane >> 3) & 1) * 8;
        offB[njp] = (uint32_t)(BS_L + row * 72 + col) * 2;
    }
    int P    = w & 1;
    int nblk = (w >> 1) * 16;
    uint32_t offTA, offTB;
    {
        int arow = nblk + (lane & 7) + ((lane >> 3) & 1) * 8;
        int acol = ((lane >> 4) & 1) * 8;
        offTA = sb + (uint32_t)(AP_H + (1 - P) * 5120 + arow * 40 + acol) * 2;
        int brow = (lane & 7) + ((lane >> 4) & 1) * 8;
        int bcol = ((lane >> 3) & 1) * 8;
        offTB = sb + (uint32_t)(TP_H + P * 1280 + brow * 40 + bcol) * 2;
    }

    int l0 = kc * 32;
    float4 qv[4], kv[4];

#define LDG_IT(LIDX)                                                           \
    {                                                                          \
        const float* sq_ = qb + (size_t)(n * LSEG + (LIDX)) * ROWSTRIDE + q16; \
        const float* sk_ = kb + (size_t)(n * LSEG + (LIDX)) * ROWSTRIDE + q16; \
        _Pragma("unroll")                                                      \
        for (int i_ = 0; i_ < 4; i_++) {                                       \
            qv[i_] = *(const float4*)(sq_ + 4 * i_);                           \
            kv[i_] = *(const float4*)(sk_ + 4 * i_);                           \
        }                                                                      \
    }

#define STAGE(BUF)                                                             \
    {                                                                          \
        __half* bufp = sh + (BUF) * BUFH;                                      \
        uint4 ua_, ub_;                                                        \
        ua_.x = h2u(qv[0].x, qv[0].y); ua_.y = h2u(qv[0].z, qv[0].w);          \
        ua_.z = h2u(qv[1].x, qv[1].y); ua_.w = h2u(qv[1].z, qv[1].w);          \
        ub_.x = h2u(qv[2].x, qv[2].y); ub_.y = h2u(qv[2].z, qv[2].w);          \
        ub_.z = h2u(qv[3].x, qv[3].y); ub_.w = h2u(qv[3].z, qv[3].w);          \
        *(uint4*)&bufp[AS_L + n * 72 + q16]     = ua_;                         \
        *(uint4*)&bufp[AS_L + n * 72 + q16 + 8] = ub_;                         \
        float e0_=kv[0].x, e1_=kv[0].z, e2_=kv[1].x, e3_=kv[1].z;              \
        float e4_=kv[2].x, e5_=kv[2].z, e6_=kv[3].x, e7_=kv[3].z;              \
        float o0_=kv[0].y, o1_=kv[0].w, o2_=kv[1].y, o3_=kv[1].w;              \
        float o4_=kv[2].y, o5_=kv[2].w, o6_=kv[3].y, o7_=kv[3].w;              \
        float se_ = ((e0_+e1_)+(e2_+e3_)) + ((e4_+e5_)+(e6_+e7_));             \
        float so_ = ((o0_+o1_)+(o2_+o3_)) + ((o4_+o5_)+(o6_+o7_));             \
        se_ += __shfl_xor_sync(0xffffffffu, se_, 1);                           \
        se_ += __shfl_xor_sync(0xffffffffu, se_, 2);                           \
        so_ += __shfl_xor_sync(0xffffffffu, so_, 1);                           \
        so_ += __shfl_xor_sync(0xffffffffu, so_, 2);                           \
        se_ *= (1.0f / 64.0f);                                                 \
        so_ *= (1.0f / 64.0f);                                                 \
        uint4 ra_, rb_;                                                        \
        ra_.x = h2u(0.5f*e0_+se_, 0.5f*o0_+so_);                               \
        ra_.y = h2u(0.5f*e1_+se_, 0.5f*o1_+so_);                               \
        ra_.z = h2u(0.5f*e2_+se_, 0.5f*o2_+so_);                               \
        ra_.w = h2u(0.5f*e3_+se_, 0.5f*o3_+so_);                               \
        rb_.x = h2u(0.5f*e4_+se_, 0.5f*o4_+so_);                               \
        rb_.y = h2u(0.5f*e5_+se_, 0.5f*o5_+so_);                               \
        rb_.z = h2u(0.5f*e6_+se_, 0.5f*o6_+so_);                               \
        rb_.w = h2u(0.5f*e7_+se_, 0.5f*o7_+so_);                               \
        *(uint4*)&bufp[BS_L + n * 72 + q16]     = ra_;                         \
        *(uint4*)&bufp[BS_L + n * 72 + q16 + 8] = rb_;                         \
        uint4 pe_, po_;                                                        \
        pe_.x = h2u(e0_, e1_); pe_.y = h2u(e2_, e3_);                          \
        pe_.z = h2u(e4_, e5_); pe_.w = h2u(e6_, e7_);                          \
        po_.x = h2u(o0_, o1_); po_.y = h2u(o2_, o3_);                          \
        po_.z = h2u(o4_, o5_); po_.w = h2u(o6_, o7_);                          \
        *(uint4*)&sh[AP_H + n * 40 + q8]        = pe_;                         \
        *(uint4*)&sh[AP_H + 5120 + n * 40 + q8] = po_;                         \
    }

#define TRANSFORM(BUF)                                                         \
    {                                                                          \
        __half* bsim = sh + (BUF) * BUFH + BS_L;                               \
        float cacc[4][4];                                                      \
        _Pragma("unroll")                                                      \
        for (int j8_ = 0; j8_ < 4; j8_++)                                      \
            _Pragma("unroll")                                                  \
            for (int r_ = 0; r_ < 4; r_++) cacc[j8_][r_] = 0.0f;               \
        _Pragma("unroll")                                                      \
        for (int s_ = 0; s_ < 2; s_++) {                                       \
            unsigned a_[4];                                                    \
            ldsm_x4(a_, offTA + s_ * 32);                                      \
            _Pragma("unroll")                                                  \
            for (int dt_ = 0; dt_ < 2; dt_++) {                                \
                unsigned bb_[4];                                               \
                ldsm_x4(bb_, offTB + dt_ * (16 * 40 * 2) + s_ * 32);           \
                mma_f16(cacc[dt_ * 2 + 0], a_, bb_[0], bb_[1]);                \
                mma_f16(cacc[dt_ * 2 + 1], a_, bb_[2], bb_[3]);                \
            }                                                                  \
        }                                                                      \
        _Pragma("unroll")                                                      \
        for (int j8_ = 0; j8_ < 4; j8_++) {                                    \
            int col0_ = P + 2 * (j8_ * 8 + 2 * t4);                            \
            int row_  = nblk + g;                                              \
            bsim[(128 + row_) * 72 + col0_]         = __float2half(cacc[j8_][0]); \
            bsim[(128 + row_) * 72 + col0_ + 2]     = __float2half(cacc[j8_][1]); \
            bsim[(128 + row_ + 8) * 72 + col0_]     = __float2half(cacc[j8_][2]); \
            bsim[(128 + row_ + 8) * 72 + col0_ + 2] = __float2half(cacc[j8_][3]); \
        }                                                                      \
    }

    // prologue
    LDG_IT(l0);
    __syncthreads();
    STAGE(0);
    LDG_IT(l0 + 1);
    __syncthreads();
    TRANSFORM(0);
    __syncthreads();

    for (int il = 0; il < 32; il++) {
        int buf = il & 1;
        if (il + 1 < 32) {
            STAGE(buf ^ 1);
            if (il + 2 < 32) LDG_IT(l0 + il + 2);
        }
        {
            uint32_t bb0 = sb + (uint32_t)(buf * BUFH) * 2;
#pragma unroll
            for (int s = 0; s < 4; s++) {
                uint32_t so_ = s * 32;
                unsigned a[2][4];
#pragma unroll
                for (int mi = 0; mi < 2; mi++) ldsm_x4(a[mi], bb0 + offA[mi] + so_);
#pragma unroll
                for (int njp = 0; njp < 4; njp++) {
                    unsigned bbv[4];
                    ldsm_x4(bbv, bb0 + offB[njp] + so_);
#pragma unroll
                    for (int mi = 0; mi < 2; mi++) {
                        mma_f16(dacc[mi][2 * njp],     a[mi], bbv[0], bbv[1]);
                        mma_f16(dacc[mi][2 * njp + 1], a[mi], bbv[2], bbv[3]);
                    }
                }
            }
        }
        __syncthreads();
        if (il + 1 < 32) {
            TRANSFORM(buf ^ 1);
            __syncthreads();
        }
    }

    // epilogue: fp16 partials
    __half* cp = g_CpartH + ((size_t)(kc * BH + bh) * MSEG) * 256;
#pragma unroll
    for (int mi = 0; mi < 2; mi++) {
#pragma unroll
        for (int nj = 0; nj < 8; nj++) {
            int r = m0 + mi * 16 + g;
            int c = j0 + nj * 8 + 2 * t4;
            *(unsigned*)(cp + (size_t)r * 256 + c)       = h2u(dacc[mi][nj][0], dacc[mi][nj][1]);
            *(unsigned*)(cp + (size_t)(r + 8) * 256 + c) = h2u(dacc[mi][nj][2], dacc[mi][nj][3]);
        }
    }
}

// ---------------------------------------------------------------------------
// Kernel 2: reduce fp16 partials (fp32 accum), |S|/512, row softmax -> g_Ah
// ---------------------------------------------------------------------------
__global__ __launch_bounds__(256) void softmax_k() {
    int bh   = blockIdx.x;
    int m    = blockIdx.y * 8 + (threadIdx.x >> 5);
    int lane = threadIdx.x & 31;

    float t[4];
#pragma unroll
    for (int u = 0; u < 4; u++) {
        int n = lane + u * 32;
        float sre = 0.0f, sim = 0.0f;
#pragma unroll
        for (int p = 0; p < KCH; p++) {
            const __half* cp = g_CpartH + (((size_t)p * BH + bh) * MSEG + m) * 256;
            sre += __half2float(cp[n]);
            sim += __half2float(cp[n + 128]);
        }
        t[u] = sqrtf(sre * sre + sim * sim) * (1.0f / 512.0f);
    }
    float mx = fmaxf(fmaxf(t[0], t[1]), fmaxf(t[2], t[3]));
#pragma unroll
    for (int o = 16; o; o >>= 1) mx = fmaxf(mx, __shfl_xor_sync(0xffffffffu, mx, o));
    float e[4], s = 0.0f;
#pragma unroll
    for (int u = 0; u < 4; u++) { e[u] = expf(t[u] - mx); s += e[u]; }
#pragma unroll
    for (int o = 16; o; o >>= 1) s += __shfl_xor_sync(0xffffffffu, s, o);
    float inv = 1.0f / s;
    __half* arow = g_Ah + ((size_t)bh * MSEG + m) * MSEG;
#pragma unroll
    for (int u = 0; u < 4; u++) arow[lane + u * 32] = __float2half(e[u] * inv);
}

// ---------------------------------------------------------------------------
// Kernel 3: out = A @ v, FP16 mma. A resident, LPB=16, single sync per l.
// grid 256 = one resident wave at 2 CTA/SM.  (unchanged from R15)
// ---------------------------------------------------------------------------
__global__ __launch_bounds__(256, 2) void v_gemm_h3(const float* __restrict__ v,
                                                    float* __restrict__ out) {
    extern __shared__ char dynsm[];
    __half (*As)[136]  = (__half(*)[136])dynsm;
    __half2 (*vsp)[72] = (__half2(*)[72])(dynsm + 128 * 136 * 2);

    int bx = blockIdx.x;
    int lg = bx & 3;
    int bh = bx >> 2;
    int b  = bh >> 4, h = bh & 15;
    int tid  = threadIdx.x;
    int lane = tid & 31;
    int w    = tid >> 5;
    int g = lane >> 2, t = lane & 3;
    int m0 = (w >> 1) * 32;
    int d0 = (w & 1) * 32;

    const __half* Abase = g_Ah + (size_t)bh * MSEG * MSEG;
    const float* vbh    = v + (size_t)b * BSTRIDE + h * DDIM;
    float* obh          = out + (size_t)b * BSTRIDE + h * DDIM;

    int kpV = tid >> 4;
    int d4V = tid & 15;

    float4 pv[8];
    {
        const float* vb = vbh + (size_t)(lg * LPB) * ROWSTRIDE;
#pragma unroll
        for (int i = 0; i < 4; i++) {
            int kp = kpV + 16 * i;
            pv[2 * i]     = *(const float4*)(vb + (size_t)(2 * kp) * SEGSTRIDE + d4V * 4);
            pv[2 * i + 1] = *(const float4*)(vb + (size_t)(2 * kp + 1) * SEGSTRIDE + d4V * 4);
        }
    }

#pragma unroll
    for (int i = 0; i < 8; i++) {
        int idx = tid + i * 256;
        int m = idx >> 4, c = idx & 15;
        uint4 u = *(const uint4*)(Abase + (size_t)m * MSEG + c * 8);
        *(uint4*)&As[m][c * 8] = u;
    }

    for (int il = 0; il < LPB; il++) {
        int l   = lg * LPB + il;
        int buf = (il & 1) * 64;
#pragma unroll
        for (int i = 0; i < 4; i++) {
            int kp = kpV + 16 * i;
            uint4 u;
            u.x = h2u(pv[2 * i].x, pv[2 * i + 1].x);
            u.y = h2u(pv[2 * i].y, pv[2 * i + 1].y);
            u.z = h2u(pv[2 * i].z, pv[2 * i + 1].z);
            u.w = h2u(pv[2 * i].w, pv[2 * i + 1].w);
            *(uint4*)&vsp[buf + kp][d4V * 4] = u;
        }
        if (il + 1 < LPB) {
            const float* vb = vbh + (size_t)(l + 1) * ROWSTRIDE;
#pragma unroll
            for (int i = 0; i < 4; i++) {
                int kp = kpV + 16 * i;
                pv[2 * i]     = *(const float4*)(vb + (size_t)(2 * kp) * SEGSTRIDE + d4V * 4);
                pv[2 * i + 1] = *(const float4*)(vb + (size_t)(2 * kp + 1) * SEGSTRIDE + d4V * 4);
            }
        }
        __syncthreads();

        float dacc[2][4][4];
#pragma unroll
        for (int mi = 0; mi < 2; mi++)
#pragma unroll
            for (int dj = 0; dj < 4; dj++)
#pragma unroll
                for (int r = 0; r < 4; r++) dacc[mi][dj][r] = 0.0f;

#pragma unroll
        for (int s = 0; s < 8; s++) {
            int kb16 = s * 16;
            unsigned bb[4][2];
#pragma unroll
            for (int dj = 0; dj < 4; dj++) {
                int c = d0 + dj * 8 + g;
                bb[dj][0] = *(const unsigned*)&vsp[buf + s * 8 + t][c];
                bb[dj][1] = *(const unsigned*)&vsp[buf + s * 8 + t + 4][c];
            }
#pragma unroll
            for (int mi = 0; mi < 2; mi++) {
                int r = m0 + mi * 16 + g;
                unsigned a[4];
                a[0] = *(const unsigned*)&As[r][kb16 + 2 * t];
                a[1] = *(const unsigned*)&As[r + 8][kb16 + 2 * t];
                a[2] = *(const unsigned*)&As[r][kb16 + 2 * t + 8];
                a[3] = *(const unsigned*)&As[r + 8][kb16 + 2 * t + 8];
#pragma unroll
                for (int dj = 0; dj < 4; dj++) mma_f16(dacc[mi][dj], a, bb[dj][0], bb[dj][1]);
            }
        }

        float* obase = obh + (size_t)l * ROWSTRIDE;
#pragma unroll
        for (int mi = 0; mi < 2; mi++) {
#pragma unroll
            for (int dj = 0; dj < 4; dj++) {
                int r = m0 + mi * 16 + g;
                int c = d0 + dj * 8 + 2 * t;
                *(float2*)(obase + (size_t)r * SEGSTRIDE + c)       = make_float2(dacc[mi][dj][0], dacc[mi][dj][1]);
                *(float2*)(obase + (size_t)(r + 8) * SEGSTRIDE + c) = make_float2(dacc[mi][dj][2], dacc[mi][dj][3]);
            }
        }
    }
}

#define VG_SMEM (128 * 136 * 2 + 2 * 64 * 72 * 4)

// ---------------------------------------------------------------------------
extern "C" void kernel_launch(void* const* d_in, const int* in_sizes, int n_in,
                              void* d_out, int out_size) {
    const float* q = (const float*)d_in[0];
    const float* k = (const float*)d_in[1];
    const float* v = (const float*)d_in[2];
    float* out = (float*)d_out;

    cudaFuncSetAttribute(scores_fused3, cudaFuncAttributeMaxDynamicSharedMemorySize, FS_SMEM);
    cudaFuncSetAttribute(v_gemm_h3, cudaFuncAttributeMaxDynamicSharedMemorySize, VG_SMEM);

    scores_fused3<<<dim3(KCH, BH), 512, FS_SMEM>>>(q, k);
    softmax_k<<<dim3(BH, 16), 256>>>();
    v_gemm_h3<<<BH * (LSEG / LPB), 256, VG_SMEM>>>(v, out);
}